// round 1
// baseline (speedup 1.0000x reference)
#include <cuda_runtime.h>
#include <math.h>

#define N_USERS 100000
#define N_ITEMS 50000
#define BATCH   64
#define ORDER   8
#define FLATNESS 2

// ---------------- scratch (no allocation allowed -> device globals) ----------
__device__ float g_ta [(size_t)N_ITEMS * BATCH];   // t0 / t2 ping
__device__ float g_tb [(size_t)N_ITEMS * BATCH];   // t1 pong
__device__ float g_acc[(size_t)N_ITEMS * BATCH];   // output accumulator (item-major)
__device__ float g_y  [(size_t)N_USERS * BATCH];   // user-side intermediate
__device__ float g_z  [(size_t)N_ITEMS * BATCH];   // item-side intermediate

// ---------------- transpose: signal [B][N] -> [N][B] -------------------------
__global__ void transpose_in(const float* __restrict__ src, float* __restrict__ dst)
{
    __shared__ float tile[32][33];
    int i0 = blockIdx.x * 32;
    int b0 = blockIdx.y * 32;
#pragma unroll
    for (int k = 0; k < 4; k++) {
        int b = b0 + threadIdx.y + k * 8;
        int i = i0 + threadIdx.x;
        if (i < N_ITEMS)
            tile[threadIdx.y + k * 8][threadIdx.x] = src[(size_t)b * N_ITEMS + i];
    }
    __syncthreads();
#pragma unroll
    for (int k = 0; k < 4; k++) {
        int i = i0 + threadIdx.y + k * 8;
        int b = b0 + threadIdx.x;
        if (i < N_ITEMS)
            dst[(size_t)i * BATCH + b] = tile[threadIdx.x][threadIdx.y + k * 8];
    }
}

// ---------------- transpose: acc [N][B] -> out [B][N] -------------------------
__global__ void transpose_out(const float* __restrict__ src, float* __restrict__ dst)
{
    __shared__ float tile[32][33];
    int i0 = blockIdx.x * 32;
    int b0 = blockIdx.y * 32;
#pragma unroll
    for (int k = 0; k < 4; k++) {
        int i = i0 + threadIdx.y + k * 8;
        int b = b0 + threadIdx.x;
        if (i < N_ITEMS)
            tile[threadIdx.y + k * 8][threadIdx.x] = src[(size_t)i * BATCH + b];
    }
    __syncthreads();
#pragma unroll
    for (int k = 0; k < 4; k++) {
        int b = b0 + threadIdx.y + k * 8;
        int i = i0 + threadIdx.x;
        if (i < N_ITEMS)
            dst[(size_t)b * N_ITEMS + i] = tile[threadIdx.x][threadIdx.y + k * 8];
    }
}

// ---------------- edge-parallel SpMM scatter ---------------------------------
// y[dst[e]][:] += vals[e] * x[src[e]][:]    (64-wide rows, 16 lanes x float4)
__global__ void spmm_scatter(const float* __restrict__ x, float* __restrict__ y,
                             const int* __restrict__ sidx, const int* __restrict__ didx,
                             const float* __restrict__ vals, int nnz)
{
    long long gid = (long long)blockIdx.x * blockDim.x + threadIdx.x;
    int e = (int)(gid >> 4);
    if (e >= nnz) return;
    int l = (int)(gid & 15);

    int   s = __ldg(&sidx[e]);
    int   d = __ldg(&didx[e]);
    float v = __ldg(&vals[e]);

    const float4 xv = *(const float4*)(x + (size_t)s * BATCH + l * 4);
    float4 r;
    r.x = v * xv.x; r.y = v * xv.y; r.z = v * xv.z; r.w = v * xv.w;

    float* yp = y + (size_t)d * BATCH + l * 4;
    asm volatile("red.global.add.v4.f32 [%0], {%1,%2,%3,%4};"
                 :: "l"(yp), "f"(r.x), "f"(r.y), "f"(r.z), "f"(r.w)
                 : "memory");
}

// ---------------- Chebyshev elementwise combines -----------------------------
// t1 = t0 - 2z ; acc = c0*t0 + c1*t1
__global__ void cheby_init(const float* __restrict__ t0, const float* __restrict__ z,
                           float* __restrict__ t1, float* __restrict__ acc,
                           float c0, float c1, int n4)
{
    int i = blockIdx.x * blockDim.x + threadIdx.x;
    if (i >= n4) return;
    float4 a  = ((const float4*)t0)[i];
    float4 zz = ((const float4*)z)[i];
    float4 b;
    b.x = a.x - 2.f * zz.x; b.y = a.y - 2.f * zz.y;
    b.z = a.z - 2.f * zz.z; b.w = a.w - 2.f * zz.w;
    ((float4*)t1)[i] = b;
    float4 o;
    o.x = c0 * a.x + c1 * b.x; o.y = c0 * a.y + c1 * b.y;
    o.z = c0 * a.z + c1 * b.z; o.w = c0 * a.w + c1 * b.w;
    ((float4*)acc)[i] = o;
}

// t2 = 2*(t1 - 2z) - t0, written IN PLACE over t0 ; acc += ck*t2
__global__ void cheby_step(float* t0io, const float* __restrict__ t1,
                           const float* __restrict__ z, float* __restrict__ acc,
                           float ck, int n4)
{
    int i = blockIdx.x * blockDim.x + threadIdx.x;
    if (i >= n4) return;
    float4 a  = ((float4*)t0io)[i];
    float4 b  = ((const float4*)t1)[i];
    float4 zz = ((const float4*)z)[i];
    float4 t2;
    t2.x = 2.f * b.x - 4.f * zz.x - a.x;
    t2.y = 2.f * b.y - 4.f * zz.y - a.y;
    t2.z = 2.f * b.z - 4.f * zz.z - a.z;
    t2.w = 2.f * b.w - 4.f * zz.w - a.w;
    ((float4*)t0io)[i] = t2;
    float4 o = ((float4*)acc)[i];
    o.x += ck * t2.x; o.y += ck * t2.y; o.z += ck * t2.z; o.w += ck * t2.w;
    ((float4*)acc)[i] = o;
}

// ---------------- host: replicate cheby_coeffs in double ----------------------
static void compute_coeffs(float c[ORDER + 1])
{
    const int order = ORDER;
    double tgt[ORDER + 1], nodes[ORDER + 1];
    for (int x = 0; x <= order; x++) {
        double v = cos((double)(order - x) / order * M_PI);
        v = nearbyint(v * 1000.0) / 1000.0;                 // np.round(.,3), ties-to-even
        double t = (v < 0.0) ? pow(-v, (double)FLATNESS) * 0.5 + 0.5
                             : pow(v, (double)FLATNESS) * (-0.5) + 0.5;
        tgt[x] = nearbyint(t * 1000.0) / 1000.0;
    }
    for (int k = 1; k <= order + 1; k++)
        nodes[k - 1] = cos((order + 1 + 0.5 - k) / (double)(order + 1) * M_PI);

    double P0[ORDER + 1], P1[ORDER + 1], P2[ORDER + 1];
    double s0 = 0.0, s1 = 0.0;
    for (int i = 0; i <= order; i++) {
        P0[i] = tgt[i];
        P1[i] = nodes[i] * tgt[i];
        s0 += P0[i]; s1 += P1[i];
    }
    c[0] = (float)(s0 * (2.0 / (order + 1)) / 2.0);
    c[1] = (float)(s1 * (2.0 / (order + 1)));
    for (int k = 2; k <= order; k++) {
        double s = 0.0;
        for (int i = 0; i <= order; i++) {
            P2[i] = 2.0 * nodes[i] * P1[i] - P0[i];
            s += P2[i];
        }
        c[k] = (float)(s * (2.0 / (order + 1)));
        for (int i = 0; i <= order; i++) { P0[i] = P1[i]; P1[i] = P2[i]; }
    }
}

// ---------------- launch ------------------------------------------------------
extern "C" void kernel_launch(void* const* d_in, const int* in_sizes, int n_in,
                              void* d_out, int out_size)
{
    const float* signal = (const float*)d_in[0];
    const float* vals   = (const float*)d_in[1];
    const int*   row    = (const int*)d_in[2];
    const int*   col    = (const int*)d_in[3];
    const int    nnz    = in_sizes[1];

    float c[ORDER + 1];
    compute_coeffs(c);

    float *ta, *tb, *acc, *y, *z;
    cudaGetSymbolAddress((void**)&ta,  g_ta);
    cudaGetSymbolAddress((void**)&tb,  g_tb);
    cudaGetSymbolAddress((void**)&acc, g_acc);
    cudaGetSymbolAddress((void**)&y,   g_y);
    cudaGetSymbolAddress((void**)&z,   g_z);

    const size_t ybytes = sizeof(float) * (size_t)N_USERS * BATCH;
    const size_t zbytes = sizeof(float) * (size_t)N_ITEMS * BATCH;

    dim3 tblk(32, 8);
    dim3 tgrd((N_ITEMS + 31) / 32, (BATCH + 31) / 32);

    const int spmm_blocks = (int)(((long long)nnz * 16 + 255) / 256);
    const int n4          = N_ITEMS * BATCH / 4;
    const int ew_blocks   = (n4 + 255) / 256;

    // s (item-major)
    transpose_in<<<tgrd, tblk>>>(signal, ta);

    // t1 = lap(t0) ; acc = c0*t0 + c1*t1
    cudaMemsetAsync(y, 0, ybytes);
    spmm_scatter<<<spmm_blocks, 256>>>(ta, y, col, row, vals, nnz);
    cudaMemsetAsync(z, 0, zbytes);
    spmm_scatter<<<spmm_blocks, 256>>>(y, z, row, col, vals, nnz);
    cheby_init<<<ew_blocks, 256>>>(ta, z, tb, acc, c[0], c[1], n4);

    float* p0 = ta;   // t_{k-2}
    float* p1 = tb;   // t_{k-1}
    for (int k = 2; k <= ORDER; k++) {
        cudaMemsetAsync(y, 0, ybytes);
        spmm_scatter<<<spmm_blocks, 256>>>(p1, y, col, row, vals, nnz);
        cudaMemsetAsync(z, 0, zbytes);
        spmm_scatter<<<spmm_blocks, 256>>>(y, z, row, col, vals, nnz);
        // t2 overwrites p0 in place; acc += c[k]*t2
        cheby_step<<<ew_blocks, 256>>>(p0, p1, z, acc, c[k], n4);
        float* t = p0; p0 = p1; p1 = t;
    }

    transpose_out<<<tgrd, tblk>>>(acc, (float*)d_out);
}

// round 2
// speedup vs baseline: 2.1082x; 2.1082x over previous
#include <cuda_runtime.h>
#include <math.h>

#define N_USERS 100000
#define N_ITEMS 50000
#define BATCH   64
#define ORDER   8
#define FLATNESS 2
#define MAX_NNZ 1600000

#define SCAN_T 256
#define SCAN_E 8   // 2048 elements per scan block

// ---------------- scratch (no allocation allowed -> device globals) ----------
__device__ float g_ta [(size_t)N_ITEMS * BATCH];    // t0 / t2 ping
__device__ float g_tb [(size_t)N_ITEMS * BATCH];    // t1 pong
__device__ float g_acc[(size_t)N_ITEMS * BATCH];    // output accumulator (item-major)
__device__ float g_y  [(size_t)N_USERS * BATCH];    // user-side intermediate

__device__ int  g_ptru[N_USERS + 1];
__device__ int  g_ptri[N_ITEMS + 1];
__device__ int  g_curu[N_USERS];
__device__ int  g_curi[N_ITEMS];
__device__ int  g_part[128];                         // scan block partials (<=49)
__device__ int2 g_evr[MAX_NNZ];                      // (col, val_bits) sorted by row
__device__ int2 g_evc[MAX_NNZ];                      // (row, val_bits) sorted by col

// ---------------- transposes --------------------------------------------------
__global__ void transpose_in(const float* __restrict__ src, float* __restrict__ dst)
{
    __shared__ float tile[32][33];
    int i0 = blockIdx.x * 32, b0 = blockIdx.y * 32;
#pragma unroll
    for (int k = 0; k < 4; k++) {
        int b = b0 + threadIdx.y + k * 8, i = i0 + threadIdx.x;
        if (i < N_ITEMS) tile[threadIdx.y + k * 8][threadIdx.x] = src[(size_t)b * N_ITEMS + i];
    }
    __syncthreads();
#pragma unroll
    for (int k = 0; k < 4; k++) {
        int i = i0 + threadIdx.y + k * 8, b = b0 + threadIdx.x;
        if (i < N_ITEMS) dst[(size_t)i * BATCH + b] = tile[threadIdx.x][threadIdx.y + k * 8];
    }
}

__global__ void transpose_out(const float* __restrict__ src, float* __restrict__ dst)
{
    __shared__ float tile[32][33];
    int i0 = blockIdx.x * 32, b0 = blockIdx.y * 32;
#pragma unroll
    for (int k = 0; k < 4; k++) {
        int i = i0 + threadIdx.y + k * 8, b = b0 + threadIdx.x;
        if (i < N_ITEMS) tile[threadIdx.y + k * 8][threadIdx.x] = src[(size_t)i * BATCH + b];
    }
    __syncthreads();
#pragma unroll
    for (int k = 0; k < 4; k++) {
        int b = b0 + threadIdx.y + k * 8, i = i0 + threadIdx.x;
        if (i < N_ITEMS) dst[(size_t)b * N_ITEMS + i] = tile[threadIdx.x][threadIdx.y + k * 8];
    }
}

// ---------------- CSR/CSC build ----------------------------------------------
__global__ void hist_kernel(const int* __restrict__ row, const int* __restrict__ col,
                            int* __restrict__ degu, int* __restrict__ degi, int nnz)
{
    int e = blockIdx.x * blockDim.x + threadIdx.x;
    if (e >= nnz) return;
    atomicAdd(&degu[row[e]], 1);
    atomicAdd(&degi[col[e]], 1);
}

__global__ void scan_phase1(const int* __restrict__ deg, int* __restrict__ ptr,
                            int* __restrict__ partial, int n)
{
    __shared__ int wsum[8];
    int base = blockIdx.x * SCAN_T * SCAN_E + threadIdx.x * SCAN_E;
    int v[SCAN_E], t = 0;
#pragma unroll
    for (int k = 0; k < SCAN_E; k++) {
        int i = base + k;
        v[k] = (i < n) ? deg[i] : 0;
        t += v[k];
    }
    int lane = threadIdx.x & 31, wid = threadIdx.x >> 5;
    int s = t;
#pragma unroll
    for (int o = 1; o < 32; o <<= 1) {
        int u = __shfl_up_sync(0xffffffff, s, o);
        if (lane >= o) s += u;
    }
    if (lane == 31) wsum[wid] = s;
    __syncthreads();
    if (wid == 0) {
        int w = (lane < 8) ? wsum[lane] : 0;
#pragma unroll
        for (int o = 1; o < 8; o <<= 1) {
            int u = __shfl_up_sync(0xffffffff, w, o);
            if (lane >= o) w += u;
        }
        if (lane < 8) wsum[lane] = w;
    }
    __syncthreads();
    int run = s - t + (wid ? wsum[wid - 1] : 0);   // block-local exclusive
#pragma unroll
    for (int k = 0; k < SCAN_E; k++) {
        int i = base + k;
        if (i < n) ptr[i] = run;
        run += v[k];
    }
    if (threadIdx.x == SCAN_T - 1) partial[blockIdx.x] = wsum[7];
}

__global__ void scan_phase2(int* partial, int nb)   // launch 32 threads, nb <= 64
{
    int lane = threadIdx.x;
    int a = (lane < nb) ? partial[lane] : 0;
    int b = (lane + 32 < nb) ? partial[lane + 32] : 0;
    int sa = a, sb = b;
#pragma unroll
    for (int o = 1; o < 32; o <<= 1) {
        int u = __shfl_up_sync(0xffffffff, sa, o); if (lane >= o) sa += u;
        int w = __shfl_up_sync(0xffffffff, sb, o); if (lane >= o) sb += w;
    }
    int tot_a = __shfl_sync(0xffffffff, sa, 31);
    if (lane < nb)      partial[lane]      = sa - a;          // exclusive
    if (lane + 32 < nb) partial[lane + 32] = sb - b + tot_a;
}

__global__ void scan_phase3(int* __restrict__ ptr, int* __restrict__ cursor,
                            const int* __restrict__ partial, int n, int total)
{
    int off = partial[blockIdx.x];
    int base = blockIdx.x * SCAN_T * SCAN_E;
    for (int k = threadIdx.x; k < SCAN_T * SCAN_E; k += SCAN_T) {
        int i = base + k;
        if (i < n) { int p = ptr[i] + off; ptr[i] = p; cursor[i] = p; }
    }
    if (blockIdx.x == 0 && threadIdx.x == 0) ptr[n] = total;
}

__global__ void build_lists(const int* __restrict__ row, const int* __restrict__ col,
                            const float* __restrict__ vals,
                            int* __restrict__ cu, int* __restrict__ ci,
                            int2* __restrict__ evr, int2* __restrict__ evc, int nnz)
{
    int e = blockIdx.x * blockDim.x + threadIdx.x;
    if (e >= nnz) return;
    int r = row[e], c = col[e];
    int vb = __float_as_int(vals[e]);
    int pu = atomicAdd(&cu[r], 1);
    evr[pu] = make_int2(c, vb);
    int pc = atomicAdd(&ci[c], 1);
    evc[pc] = make_int2(r, vb);
}

// ---------------- gather SpMM: one warp per output row ------------------------
// y[r] = sum_{j in seg(r)} val_j * x[idx_j]   (64 floats, lane holds float2)
__global__ void __launch_bounds__(256) spmm_user(
    const float* __restrict__ x, float* __restrict__ y,
    const int2* __restrict__ ev, const int* __restrict__ ptr)
{
    int r = blockIdx.x * 8 + (threadIdx.x >> 5);
    if (r >= N_USERS) return;
    int lane = threadIdx.x & 31;
    int j = __ldg(&ptr[r]), e = __ldg(&ptr[r + 1]);
    float ax = 0.f, ay = 0.f;
#pragma unroll 4
    for (; j < e; j++) {
        int2 ed = __ldg(&ev[j]);
        float v = __int_as_float(ed.y);
        float2 xv = __ldg((const float2*)(x + ((size_t)ed.x << 6) + (lane << 1)));
        ax = fmaf(v, xv.x, ax);
        ay = fmaf(v, xv.y, ay);
    }
    *(float2*)(y + ((size_t)r << 6) + (lane << 1)) = make_float2(ax, ay);
}

// item-side SpMM + fused Chebyshev init:  z = seg_sum;  t1 = t0 - 2z;
// acc = c0*t0 + c1*t1
__global__ void __launch_bounds__(256) spmm_item_first(
    const float* __restrict__ y, const int2* __restrict__ ev, const int* __restrict__ ptr,
    const float* __restrict__ t0, float* __restrict__ t1, float* __restrict__ acc,
    float c0, float c1)
{
    int r = blockIdx.x * 8 + (threadIdx.x >> 5);
    if (r >= N_ITEMS) return;
    int lane = threadIdx.x & 31;
    int j = __ldg(&ptr[r]), e = __ldg(&ptr[r + 1]);
    float zx = 0.f, zy = 0.f;
#pragma unroll 4
    for (; j < e; j++) {
        int2 ed = __ldg(&ev[j]);
        float v = __int_as_float(ed.y);
        float2 yv = __ldg((const float2*)(y + ((size_t)ed.x << 6) + (lane << 1)));
        zx = fmaf(v, yv.x, zx);
        zy = fmaf(v, yv.y, zy);
    }
    size_t o = ((size_t)r << 6) + (lane << 1);
    float2 a = *(const float2*)(t0 + o);
    float2 b = make_float2(a.x - 2.f * zx, a.y - 2.f * zy);
    *(float2*)(t1 + o) = b;
    *(float2*)(acc + o) = make_float2(c0 * a.x + c1 * b.x, c0 * a.y + c1 * b.y);
}

// item-side SpMM + fused Chebyshev step:  z = seg_sum;
// t2 = 2*t1 - 4*z - t0 (overwrites t0);  acc += ck*t2
__global__ void __launch_bounds__(256) spmm_item_step(
    const float* __restrict__ y, const int2* __restrict__ ev, const int* __restrict__ ptr,
    float* __restrict__ t0io, const float* __restrict__ t1, float* __restrict__ acc,
    float ck)
{
    int r = blockIdx.x * 8 + (threadIdx.x >> 5);
    if (r >= N_ITEMS) return;
    int lane = threadIdx.x & 31;
    int j = __ldg(&ptr[r]), e = __ldg(&ptr[r + 1]);
    float zx = 0.f, zy = 0.f;
#pragma unroll 4
    for (; j < e; j++) {
        int2 ed = __ldg(&ev[j]);
        float v = __int_as_float(ed.y);
        float2 yv = __ldg((const float2*)(y + ((size_t)ed.x << 6) + (lane << 1)));
        zx = fmaf(v, yv.x, zx);
        zy = fmaf(v, yv.y, zy);
    }
    size_t o = ((size_t)r << 6) + (lane << 1);
    float2 a = *(const float2*)(t0io + o);
    float2 b = *(const float2*)(t1 + o);
    float2 t2 = make_float2(2.f * b.x - 4.f * zx - a.x,
                            2.f * b.y - 4.f * zy - a.y);
    *(float2*)(t0io + o) = t2;
    float2 oc = *(const float2*)(acc + o);
    *(float2*)(acc + o) = make_float2(oc.x + ck * t2.x, oc.y + ck * t2.y);
}

// ---------------- host: replicate cheby_coeffs in double ----------------------
static void compute_coeffs(float c[ORDER + 1])
{
    const int order = ORDER;
    double tgt[ORDER + 1], nodes[ORDER + 1];
    for (int x = 0; x <= order; x++) {
        double v = cos((double)(order - x) / order * M_PI);
        v = nearbyint(v * 1000.0) / 1000.0;
        double t = (v < 0.0) ? pow(-v, (double)FLATNESS) * 0.5 + 0.5
                             : pow(v, (double)FLATNESS) * (-0.5) + 0.5;
        tgt[x] = nearbyint(t * 1000.0) / 1000.0;
    }
    for (int k = 1; k <= order + 1; k++)
        nodes[k - 1] = cos((order + 1 + 0.5 - k) / (double)(order + 1) * M_PI);

    double P0[ORDER + 1], P1[ORDER + 1], P2[ORDER + 1];
    double s0 = 0.0, s1 = 0.0;
    for (int i = 0; i <= order; i++) {
        P0[i] = tgt[i];
        P1[i] = nodes[i] * tgt[i];
        s0 += P0[i]; s1 += P1[i];
    }
    c[0] = (float)(s0 * (2.0 / (order + 1)) / 2.0);
    c[1] = (float)(s1 * (2.0 / (order + 1)));
    for (int k = 2; k <= order; k++) {
        double s = 0.0;
        for (int i = 0; i <= order; i++) {
            P2[i] = 2.0 * nodes[i] * P1[i] - P0[i];
            s += P2[i];
        }
        c[k] = (float)(s * (2.0 / (order + 1)));
        for (int i = 0; i <= order; i++) { P0[i] = P1[i]; P1[i] = P2[i]; }
    }
}

// ---------------- launch ------------------------------------------------------
extern "C" void kernel_launch(void* const* d_in, const int* in_sizes, int n_in,
                              void* d_out, int out_size)
{
    const float* signal = (const float*)d_in[0];
    const float* vals   = (const float*)d_in[1];
    const int*   row    = (const int*)d_in[2];
    const int*   col    = (const int*)d_in[3];
    const int    nnz    = in_sizes[1];

    float c[ORDER + 1];
    compute_coeffs(c);

    float *ta, *tb, *acc, *y;
    int *ptru, *ptri, *curu, *curi, *part;
    int2 *evr, *evc;
    cudaGetSymbolAddress((void**)&ta,   g_ta);
    cudaGetSymbolAddress((void**)&tb,   g_tb);
    cudaGetSymbolAddress((void**)&acc,  g_acc);
    cudaGetSymbolAddress((void**)&y,    g_y);
    cudaGetSymbolAddress((void**)&ptru, g_ptru);
    cudaGetSymbolAddress((void**)&ptri, g_ptri);
    cudaGetSymbolAddress((void**)&curu, g_curu);
    cudaGetSymbolAddress((void**)&curi, g_curi);
    cudaGetSymbolAddress((void**)&part, g_part);
    cudaGetSymbolAddress((void**)&evr,  g_evr);
    cudaGetSymbolAddress((void**)&evc,  g_evc);

    dim3 tblk(32, 8);
    dim3 tgrd((N_ITEMS + 31) / 32, (BATCH + 31) / 32);

    const int eblk = (nnz + 255) / 256;
    const int nbu  = (N_USERS + SCAN_T * SCAN_E - 1) / (SCAN_T * SCAN_E);  // 49
    const int nbi  = (N_ITEMS + SCAN_T * SCAN_E - 1) / (SCAN_T * SCAN_E);  // 25
    const int gu   = (N_USERS + 7) / 8;
    const int gi   = (N_ITEMS + 7) / 8;

    // ---- preprocessing: CSR (by user) + CSC (by item) ----
    cudaMemsetAsync(curu, 0, sizeof(int) * N_USERS);   // reuse as degree counters
    cudaMemsetAsync(curi, 0, sizeof(int) * N_ITEMS);
    hist_kernel<<<eblk, 256>>>(row, col, curu, curi, nnz);

    scan_phase1<<<nbu, SCAN_T>>>(curu, ptru, part, N_USERS);
    scan_phase2<<<1, 32>>>(part, nbu);
    scan_phase3<<<nbu, SCAN_T>>>(ptru, curu, part, N_USERS, nnz);

    scan_phase1<<<nbi, SCAN_T>>>(curi, ptri, part, N_ITEMS);
    scan_phase2<<<1, 32>>>(part, nbi);
    scan_phase3<<<nbi, SCAN_T>>>(ptri, curi, part, N_ITEMS, nnz);

    build_lists<<<eblk, 256>>>(row, col, vals, curu, curi, evr, evc, nnz);

    // ---- signal to item-major ----
    transpose_in<<<tgrd, tblk>>>(signal, ta);

    // ---- Chebyshev recurrence, 8 laps, all gather-based ----
    spmm_user<<<gu, 256>>>(ta, y, evr, ptru);
    spmm_item_first<<<gi, 256>>>(y, evc, ptri, ta, tb, acc, c[0], c[1]);

    float* p0 = ta;   // t_{k-2}
    float* p1 = tb;   // t_{k-1}
    for (int k = 2; k <= ORDER; k++) {
        spmm_user<<<gu, 256>>>(p1, y, evr, ptru);
        spmm_item_step<<<gi, 256>>>(y, evc, ptri, p0, p1, acc, c[k]);
        float* t = p0; p0 = p1; p1 = t;
    }

    transpose_out<<<tgrd, tblk>>>(acc, (float*)d_out);
}

// round 3
// speedup vs baseline: 2.2581x; 1.0711x over previous
#include <cuda_runtime.h>
#include <cuda_fp16.h>
#include <math.h>

#define N_USERS 100000
#define N_ITEMS 50000
#define BATCH   64
#define ORDER   8
#define FLATNESS 2
#define MAX_NNZ 1600000

#define SCAN_T 256
#define SCAN_E 8   // 2048 elements per scan block

// ---------------- scratch (no allocation allowed -> device globals) ----------
__device__ float  g_ta [(size_t)N_ITEMS * BATCH];   // t0 / t2 ping (fp32 state)
__device__ float  g_tb [(size_t)N_ITEMS * BATCH];   // t1 pong (fp32 state)
__device__ float  g_acc[(size_t)N_ITEMS * BATCH];   // output accumulator (item-major)
__device__ __half g_yh [(size_t)N_USERS * BATCH];   // user-side intermediate (half)
__device__ __half g_th [(size_t)N_ITEMS * BATCH];   // half shadow of current iterate

__device__ int  g_ptru[N_USERS + 1];
__device__ int  g_ptri[N_ITEMS + 1];
__device__ int  g_curu[N_USERS];
__device__ int  g_curi[N_ITEMS];
__device__ int  g_part[128];                         // scan block partials (<=49)
__device__ int2 g_evr[MAX_NNZ];                      // (col, val_bits) sorted by row
__device__ int2 g_evc[MAX_NNZ];                      // (row, val_bits) sorted by col

// ---------------- transposes --------------------------------------------------
// signal [B][N] -> fp32 t0 [N][B]  and half shadow
__global__ void transpose_in(const float* __restrict__ src, float* __restrict__ dst,
                             __half* __restrict__ dsth)
{
    __shared__ float tile[32][33];
    int i0 = blockIdx.x * 32, b0 = blockIdx.y * 32;
#pragma unroll
    for (int k = 0; k < 4; k++) {
        int b = b0 + threadIdx.y + k * 8, i = i0 + threadIdx.x;
        if (i < N_ITEMS) tile[threadIdx.y + k * 8][threadIdx.x] = src[(size_t)b * N_ITEMS + i];
    }
    __syncthreads();
#pragma unroll
    for (int k = 0; k < 4; k++) {
        int i = i0 + threadIdx.y + k * 8, b = b0 + threadIdx.x;
        if (i < N_ITEMS) {
            float v = tile[threadIdx.x][threadIdx.y + k * 8];
            dst [(size_t)i * BATCH + b] = v;
            dsth[(size_t)i * BATCH + b] = __float2half_rn(v);
        }
    }
}

__global__ void transpose_out(const float* __restrict__ src, float* __restrict__ dst)
{
    __shared__ float tile[32][33];
    int i0 = blockIdx.x * 32, b0 = blockIdx.y * 32;
#pragma unroll
    for (int k = 0; k < 4; k++) {
        int i = i0 + threadIdx.y + k * 8, b = b0 + threadIdx.x;
        if (i < N_ITEMS) tile[threadIdx.y + k * 8][threadIdx.x] = src[(size_t)i * BATCH + b];
    }
    __syncthreads();
#pragma unroll
    for (int k = 0; k < 4; k++) {
        int b = b0 + threadIdx.y + k * 8, i = i0 + threadIdx.x;
        if (i < N_ITEMS) dst[(size_t)b * N_ITEMS + i] = tile[threadIdx.x][threadIdx.y + k * 8];
    }
}

// ---------------- CSR/CSC build ----------------------------------------------
__global__ void hist_kernel(const int* __restrict__ row, const int* __restrict__ col,
                            int* __restrict__ degu, int* __restrict__ degi, int nnz)
{
    int e = blockIdx.x * blockDim.x + threadIdx.x;
    if (e >= nnz) return;
    atomicAdd(&degu[row[e]], 1);
    atomicAdd(&degi[col[e]], 1);
}

__global__ void scan_phase1(const int* __restrict__ deg, int* __restrict__ ptr,
                            int* __restrict__ partial, int n)
{
    __shared__ int wsum[8];
    int base = blockIdx.x * SCAN_T * SCAN_E + threadIdx.x * SCAN_E;
    int v[SCAN_E], t = 0;
#pragma unroll
    for (int k = 0; k < SCAN_E; k++) {
        int i = base + k;
        v[k] = (i < n) ? deg[i] : 0;
        t += v[k];
    }
    int lane = threadIdx.x & 31, wid = threadIdx.x >> 5;
    int s = t;
#pragma unroll
    for (int o = 1; o < 32; o <<= 1) {
        int u = __shfl_up_sync(0xffffffff, s, o);
        if (lane >= o) s += u;
    }
    if (lane == 31) wsum[wid] = s;
    __syncthreads();
    if (wid == 0) {
        int w = (lane < 8) ? wsum[lane] : 0;
#pragma unroll
        for (int o = 1; o < 8; o <<= 1) {
            int u = __shfl_up_sync(0xffffffff, w, o);
            if (lane >= o) w += u;
        }
        if (lane < 8) wsum[lane] = w;
    }
    __syncthreads();
    int run = s - t + (wid ? wsum[wid - 1] : 0);   // block-local exclusive
#pragma unroll
    for (int k = 0; k < SCAN_E; k++) {
        int i = base + k;
        if (i < n) ptr[i] = run;
        run += v[k];
    }
    if (threadIdx.x == SCAN_T - 1) partial[blockIdx.x] = wsum[7];
}

__global__ void scan_phase2(int* partial, int nb)   // launch 32 threads, nb <= 64
{
    int lane = threadIdx.x;
    int a = (lane < nb) ? partial[lane] : 0;
    int b = (lane + 32 < nb) ? partial[lane + 32] : 0;
    int sa = a, sb = b;
#pragma unroll
    for (int o = 1; o < 32; o <<= 1) {
        int u = __shfl_up_sync(0xffffffff, sa, o); if (lane >= o) sa += u;
        int w = __shfl_up_sync(0xffffffff, sb, o); if (lane >= o) sb += w;
    }
    int tot_a = __shfl_sync(0xffffffff, sa, 31);
    if (lane < nb)      partial[lane]      = sa - a;          // exclusive
    if (lane + 32 < nb) partial[lane + 32] = sb - b + tot_a;
}

// 1024 elements per block (finer than phase1 blocking for occupancy)
__global__ void scan_phase3(int* __restrict__ ptr, int* __restrict__ cursor,
                            const int* __restrict__ partial, int n, int total)
{
    int i = blockIdx.x * 1024 + threadIdx.x * 4;
    if (i < n) {
        int off = partial[i / (SCAN_T * SCAN_E)];
#pragma unroll
        for (int k = 0; k < 4; k++) {
            int j = i + k;
            if (j < n) { int p = ptr[j] + off; ptr[j] = p; cursor[j] = p; }
        }
    }
    if (blockIdx.x == 0 && threadIdx.x == 0) ptr[n] = total;
}

__global__ void build_lists(const int* __restrict__ row, const int* __restrict__ col,
                            const float* __restrict__ vals,
                            int* __restrict__ cu, int* __restrict__ ci,
                            int2* __restrict__ evr, int2* __restrict__ evc, int nnz)
{
    int e = blockIdx.x * blockDim.x + threadIdx.x;
    if (e >= nnz) return;
    int r = row[e], c = col[e];
    int vb = __float_as_int(vals[e]);
    int pu = atomicAdd(&cu[r], 1);
    evr[pu] = make_int2(c, vb);
    int pc = atomicAdd(&ci[c], 1);
    evc[pc] = make_int2(r, vb);
}

// ---------------- gather SpMM: one warp per output row ------------------------
// user side: y[r] = sum val_j * x_h[idx_j]  (half gather, fp32 accum, half store)
__global__ void __launch_bounds__(256) spmm_user(
    const __half* __restrict__ xh, __half* __restrict__ yh,
    const int2* __restrict__ ev, const int* __restrict__ ptr)
{
    int r = blockIdx.x * 8 + (threadIdx.x >> 5);
    if (r >= N_USERS) return;
    int lane = threadIdx.x & 31;
    int j = __ldg(&ptr[r]), e = __ldg(&ptr[r + 1]);
    float ax = 0.f, ay = 0.f;
#pragma unroll 4
    for (; j < e; j++) {
        int2 ed = __ldg(&ev[j]);
        float v = __int_as_float(ed.y);
        __half2 xv = __ldg((const __half2*)(xh + ((size_t)ed.x << 6) + (lane << 1)));
        float2 xf = __half22float2(xv);
        ax = fmaf(v, xf.x, ax);
        ay = fmaf(v, xf.y, ay);
    }
    *(__half2*)(yh + ((size_t)r << 6) + (lane << 1)) =
        __floats2half2_rn(ax, ay);
}

// item-side SpMM + fused Chebyshev init:  z = seg_sum(yh);  t1 = t0 - 2z;
// acc = c0*t0 + c1*t1 ;  th = half(t1)
__global__ void __launch_bounds__(256) spmm_item_first(
    const __half* __restrict__ yh, const int2* __restrict__ ev, const int* __restrict__ ptr,
    const float* __restrict__ t0, float* __restrict__ t1, float* __restrict__ acc,
    __half* __restrict__ th, float c0, float c1)
{
    int r = blockIdx.x * 8 + (threadIdx.x >> 5);
    if (r >= N_ITEMS) return;
    int lane = threadIdx.x & 31;
    int j = __ldg(&ptr[r]), e = __ldg(&ptr[r + 1]);
    float zx = 0.f, zy = 0.f;
#pragma unroll 4
    for (; j < e; j++) {
        int2 ed = __ldg(&ev[j]);
        float v = __int_as_float(ed.y);
        __half2 yv = __ldg((const __half2*)(yh + ((size_t)ed.x << 6) + (lane << 1)));
        float2 yf = __half22float2(yv);
        zx = fmaf(v, yf.x, zx);
        zy = fmaf(v, yf.y, zy);
    }
    size_t o = ((size_t)r << 6) + (lane << 1);
    float2 a = *(const float2*)(t0 + o);
    float2 b = make_float2(a.x - 2.f * zx, a.y - 2.f * zy);
    *(float2*)(t1 + o) = b;
    *(__half2*)(th + o) = __floats2half2_rn(b.x, b.y);
    *(float2*)(acc + o) = make_float2(c0 * a.x + c1 * b.x, c0 * a.y + c1 * b.y);
}

// item-side SpMM + fused Chebyshev step:  z = seg_sum(yh);
// t2 = 2*t1 - 4*z - t0 (overwrites t0);  acc += ck*t2 ;  th = half(t2)
__global__ void __launch_bounds__(256) spmm_item_step(
    const __half* __restrict__ yh, const int2* __restrict__ ev, const int* __restrict__ ptr,
    float* __restrict__ t0io, const float* __restrict__ t1, float* __restrict__ acc,
    __half* __restrict__ th, float ck)
{
    int r = blockIdx.x * 8 + (threadIdx.x >> 5);
    if (r >= N_ITEMS) return;
    int lane = threadIdx.x & 31;
    int j = __ldg(&ptr[r]), e = __ldg(&ptr[r + 1]);
    float zx = 0.f, zy = 0.f;
#pragma unroll 4
    for (; j < e; j++) {
        int2 ed = __ldg(&ev[j]);
        float v = __int_as_float(ed.y);
        __half2 yv = __ldg((const __half2*)(yh + ((size_t)ed.x << 6) + (lane << 1)));
        float2 yf = __half22float2(yv);
        zx = fmaf(v, yf.x, zx);
        zy = fmaf(v, yf.y, zy);
    }
    size_t o = ((size_t)r << 6) + (lane << 1);
    float2 a = *(const float2*)(t0io + o);
    float2 b = *(const float2*)(t1 + o);
    float2 t2 = make_float2(2.f * b.x - 4.f * zx - a.x,
                            2.f * b.y - 4.f * zy - a.y);
    *(float2*)(t0io + o) = t2;
    *(__half2*)(th + o) = __floats2half2_rn(t2.x, t2.y);
    float2 oc = *(const float2*)(acc + o);
    *(float2*)(acc + o) = make_float2(oc.x + ck * t2.x, oc.y + ck * t2.y);
}

// ---------------- host: replicate cheby_coeffs in double ----------------------
static void compute_coeffs(float c[ORDER + 1])
{
    const int order = ORDER;
    double tgt[ORDER + 1], nodes[ORDER + 1];
    for (int x = 0; x <= order; x++) {
        double v = cos((double)(order - x) / order * M_PI);
        v = nearbyint(v * 1000.0) / 1000.0;
        double t = (v < 0.0) ? pow(-v, (double)FLATNESS) * 0.5 + 0.5
                             : pow(v, (double)FLATNESS) * (-0.5) + 0.5;
        tgt[x] = nearbyint(t * 1000.0) / 1000.0;
    }
    for (int k = 1; k <= order + 1; k++)
        nodes[k - 1] = cos((order + 1 + 0.5 - k) / (double)(order + 1) * M_PI);

    double P0[ORDER + 1], P1[ORDER + 1], P2[ORDER + 1];
    double s0 = 0.0, s1 = 0.0;
    for (int i = 0; i <= order; i++) {
        P0[i] = tgt[i];
        P1[i] = nodes[i] * tgt[i];
        s0 += P0[i]; s1 += P1[i];
    }
    c[0] = (float)(s0 * (2.0 / (order + 1)) / 2.0);
    c[1] = (float)(s1 * (2.0 / (order + 1)));
    for (int k = 2; k <= order; k++) {
        double s = 0.0;
        for (int i = 0; i <= order; i++) {
            P2[i] = 2.0 * nodes[i] * P1[i] - P0[i];
            s += P2[i];
        }
        c[k] = (float)(s * (2.0 / (order + 1)));
        for (int i = 0; i <= order; i++) { P0[i] = P1[i]; P1[i] = P2[i]; }
    }
}

// ---------------- launch ------------------------------------------------------
extern "C" void kernel_launch(void* const* d_in, const int* in_sizes, int n_in,
                              void* d_out, int out_size)
{
    const float* signal = (const float*)d_in[0];
    const float* vals   = (const float*)d_in[1];
    const int*   row    = (const int*)d_in[2];
    const int*   col    = (const int*)d_in[3];
    const int    nnz    = in_sizes[1];

    float c[ORDER + 1];
    compute_coeffs(c);

    float *ta, *tb, *acc;
    __half *yh, *th;
    int *ptru, *ptri, *curu, *curi, *part;
    int2 *evr, *evc;
    cudaGetSymbolAddress((void**)&ta,   g_ta);
    cudaGetSymbolAddress((void**)&tb,   g_tb);
    cudaGetSymbolAddress((void**)&acc,  g_acc);
    cudaGetSymbolAddress((void**)&yh,   g_yh);
    cudaGetSymbolAddress((void**)&th,   g_th);
    cudaGetSymbolAddress((void**)&ptru, g_ptru);
    cudaGetSymbolAddress((void**)&ptri, g_ptri);
    cudaGetSymbolAddress((void**)&curu, g_curu);
    cudaGetSymbolAddress((void**)&curi, g_curi);
    cudaGetSymbolAddress((void**)&part, g_part);
    cudaGetSymbolAddress((void**)&evr,  g_evr);
    cudaGetSymbolAddress((void**)&evc,  g_evc);

    dim3 tblk(32, 8);
    dim3 tgrd((N_ITEMS + 31) / 32, (BATCH + 31) / 32);

    const int eblk = (nnz + 255) / 256;
    const int nbu  = (N_USERS + SCAN_T * SCAN_E - 1) / (SCAN_T * SCAN_E);  // 49
    const int nbi  = (N_ITEMS + SCAN_T * SCAN_E - 1) / (SCAN_T * SCAN_E);  // 25
    const int p3u  = (N_USERS + 1023) / 1024;
    const int p3i  = (N_ITEMS + 1023) / 1024;
    const int gu   = (N_USERS + 7) / 8;
    const int gi   = (N_ITEMS + 7) / 8;

    // ---- preprocessing: CSR (by user) + CSC (by item) ----
    cudaMemsetAsync(curu, 0, sizeof(int) * N_USERS);   // reuse as degree counters
    cudaMemsetAsync(curi, 0, sizeof(int) * N_ITEMS);
    hist_kernel<<<eblk, 256>>>(row, col, curu, curi, nnz);

    scan_phase1<<<nbu, SCAN_T>>>(curu, ptru, part, N_USERS);
    scan_phase2<<<1, 32>>>(part, nbu);
    scan_phase3<<<p3u, SCAN_T>>>(ptru, curu, part, N_USERS, nnz);

    scan_phase1<<<nbi, SCAN_T>>>(curi, ptri, part, N_ITEMS);
    scan_phase2<<<1, 32>>>(part, nbi);
    scan_phase3<<<p3i, SCAN_T>>>(ptri, curi, part, N_ITEMS, nnz);

    build_lists<<<eblk, 256>>>(row, col, vals, curu, curi, evr, evc, nnz);

    // ---- signal to item-major (fp32 state + half shadow) ----
    transpose_in<<<tgrd, tblk>>>(signal, ta, th);

    // ---- Chebyshev recurrence, 8 laps, half gathers / fp32 state ----
    spmm_user<<<gu, 256>>>(th, yh, evr, ptru);
    spmm_item_first<<<gi, 256>>>(yh, evc, ptri, ta, tb, acc, th, c[0], c[1]);

    float* p0 = ta;   // t_{k-2}
    float* p1 = tb;   // t_{k-1}
    for (int k = 2; k <= ORDER; k++) {
        spmm_user<<<gu, 256>>>(th, yh, evr, ptru);
        spmm_item_step<<<gi, 256>>>(yh, evc, ptri, p0, p1, acc, th, c[k]);
        float* t = p0; p0 = p1; p1 = t;
    }

    transpose_out<<<tgrd, tblk>>>(acc, (float*)d_out);
}

// round 4
// speedup vs baseline: 2.7741x; 1.2285x over previous
#include <cuda_runtime.h>
#include <cuda_fp16.h>
#include <math.h>

#define N_USERS 100000
#define N_ITEMS 50000
#define BATCH   64
#define ORDER   8
#define FLATNESS 2
#define MAX_NNZ 1600000

#define SCAN_T 256
#define SCAN_E 8   // 2048 elements per scan block

// ---------------- scratch (no allocation allowed -> device globals) ----------
__device__ float  g_ta [(size_t)N_ITEMS * BATCH];   // t0 / t2 ping (fp32 state)
__device__ float  g_tb [(size_t)N_ITEMS * BATCH];   // t1 pong (fp32 state)
__device__ float  g_acc[(size_t)N_ITEMS * BATCH];   // output accumulator (item-major)
__device__ __half g_yh [(size_t)N_USERS * BATCH];   // user-side intermediate (half)
__device__ __half g_th [(size_t)N_ITEMS * BATCH];   // half shadow of current iterate

__device__ int  g_ptru[N_USERS + 1];
__device__ int  g_ptri[N_ITEMS + 1];
__device__ int  g_curu[N_USERS];
__device__ int  g_curi[N_ITEMS];
__device__ int  g_part[128];
__device__ int2 g_evr[MAX_NNZ];                      // (col, val_bits) sorted by row
__device__ int2 g_evc[MAX_NNZ];                      // (row, val_bits) sorted by col

// ---------------- transposes --------------------------------------------------
__global__ void transpose_in(const float* __restrict__ src, float* __restrict__ dst,
                             __half* __restrict__ dsth)
{
    __shared__ float tile[32][33];
    int i0 = blockIdx.x * 32, b0 = blockIdx.y * 32;
#pragma unroll
    for (int k = 0; k < 4; k++) {
        int b = b0 + threadIdx.y + k * 8, i = i0 + threadIdx.x;
        if (i < N_ITEMS) tile[threadIdx.y + k * 8][threadIdx.x] = src[(size_t)b * N_ITEMS + i];
    }
    __syncthreads();
#pragma unroll
    for (int k = 0; k < 4; k++) {
        int i = i0 + threadIdx.y + k * 8, b = b0 + threadIdx.x;
        if (i < N_ITEMS) {
            float v = tile[threadIdx.x][threadIdx.y + k * 8];
            dst [(size_t)i * BATCH + b] = v;
            dsth[(size_t)i * BATCH + b] = __float2half_rn(v);
        }
    }
}

__global__ void transpose_out(const float* __restrict__ src, float* __restrict__ dst)
{
    __shared__ float tile[32][33];
    int i0 = blockIdx.x * 32, b0 = blockIdx.y * 32;
#pragma unroll
    for (int k = 0; k < 4; k++) {
        int i = i0 + threadIdx.y + k * 8, b = b0 + threadIdx.x;
        if (i < N_ITEMS) tile[threadIdx.y + k * 8][threadIdx.x] = src[(size_t)i * BATCH + b];
    }
    __syncthreads();
#pragma unroll
    for (int k = 0; k < 4; k++) {
        int b = b0 + threadIdx.y + k * 8, i = i0 + threadIdx.x;
        if (i < N_ITEMS) dst[(size_t)b * N_ITEMS + i] = tile[threadIdx.x][threadIdx.y + k * 8];
    }
}

// ---------------- CSR/CSC build ----------------------------------------------
__global__ void hist_kernel(const int* __restrict__ row, const int* __restrict__ col,
                            int* __restrict__ degu, int* __restrict__ degi, int nnz)
{
    int e = blockIdx.x * blockDim.x + threadIdx.x;
    if (e >= nnz) return;
    atomicAdd(&degu[row[e]], 1);
    atomicAdd(&degi[col[e]], 1);
}

__global__ void scan_phase1(const int* __restrict__ deg, int* __restrict__ ptr,
                            int* __restrict__ partial, int n)
{
    __shared__ int wsum[8];
    int base = blockIdx.x * SCAN_T * SCAN_E + threadIdx.x * SCAN_E;
    int v[SCAN_E], t = 0;
#pragma unroll
    for (int k = 0; k < SCAN_E; k++) {
        int i = base + k;
        v[k] = (i < n) ? deg[i] : 0;
        t += v[k];
    }
    int lane = threadIdx.x & 31, wid = threadIdx.x >> 5;
    int s = t;
#pragma unroll
    for (int o = 1; o < 32; o <<= 1) {
        int u = __shfl_up_sync(0xffffffff, s, o);
        if (lane >= o) s += u;
    }
    if (lane == 31) wsum[wid] = s;
    __syncthreads();
    if (wid == 0) {
        int w = (lane < 8) ? wsum[lane] : 0;
#pragma unroll
        for (int o = 1; o < 8; o <<= 1) {
            int u = __shfl_up_sync(0xffffffff, w, o);
            if (lane >= o) w += u;
        }
        if (lane < 8) wsum[lane] = w;
    }
    __syncthreads();
    int run = s - t + (wid ? wsum[wid - 1] : 0);
#pragma unroll
    for (int k = 0; k < SCAN_E; k++) {
        int i = base + k;
        if (i < n) ptr[i] = run;
        run += v[k];
    }
    if (threadIdx.x == SCAN_T - 1) partial[blockIdx.x] = wsum[7];
}

__global__ void scan_phase2(int* partial, int nb)
{
    int lane = threadIdx.x;
    int a = (lane < nb) ? partial[lane] : 0;
    int b = (lane + 32 < nb) ? partial[lane + 32] : 0;
    int sa = a, sb = b;
#pragma unroll
    for (int o = 1; o < 32; o <<= 1) {
        int u = __shfl_up_sync(0xffffffff, sa, o); if (lane >= o) sa += u;
        int w = __shfl_up_sync(0xffffffff, sb, o); if (lane >= o) sb += w;
    }
    int tot_a = __shfl_sync(0xffffffff, sa, 31);
    if (lane < nb)      partial[lane]      = sa - a;
    if (lane + 32 < nb) partial[lane + 32] = sb - b + tot_a;
}

__global__ void scan_phase3(int* __restrict__ ptr, int* __restrict__ cursor,
                            const int* __restrict__ partial, int n, int total)
{
    int i = blockIdx.x * 1024 + threadIdx.x * 4;
    if (i < n) {
        int off = partial[i / (SCAN_T * SCAN_E)];
#pragma unroll
        for (int k = 0; k < 4; k++) {
            int j = i + k;
            if (j < n) { int p = ptr[j] + off; ptr[j] = p; cursor[j] = p; }
        }
    }
    if (blockIdx.x == 0 && threadIdx.x == 0) ptr[n] = total;
}

__global__ void build_lists(const int* __restrict__ row, const int* __restrict__ col,
                            const float* __restrict__ vals,
                            int* __restrict__ cu, int* __restrict__ ci,
                            int2* __restrict__ evr, int2* __restrict__ evc, int nnz)
{
    int e = blockIdx.x * blockDim.x + threadIdx.x;
    if (e >= nnz) return;
    int r = row[e], c = col[e];
    int vb = __float_as_int(vals[e]);
    int pu = atomicAdd(&cu[r], 1);
    evr[pu] = make_int2(c, vb);
    int pc = atomicAdd(&ci[c], 1);
    evc[pc] = make_int2(r, vb);
}

// ---------------- wide gather core --------------------------------------------
// One warp per row. 8-lane groups: group g = lane>>3 handles edge j+g, slice
// sl = lane&7 covers halves [8sl, 8sl+8) of the 128B row. 4 edges per iter,
// one LDG.64 (edge) + one LDG.128 (gather) per iter. Accumulate fp32, then
// reduce across groups with shfl_xor(8) + shfl_xor(16).
struct Acc8 { float a[8]; };

__device__ __forceinline__ Acc8 gather_row(const __half* __restrict__ xh,
                                           const int2* __restrict__ ev,
                                           int j0, int e, int g, int sl)
{
    Acc8 r;
#pragma unroll
    for (int k = 0; k < 8; k++) r.a[k] = 0.f;
#pragma unroll 2
    for (int j = j0 + g; j < e; j += 4) {
        int2 ed = __ldg(&ev[j]);
        float v = __int_as_float(ed.y);
        uint4 q = __ldg((const uint4*)(xh + ((size_t)ed.x << 6)) + sl);
        float2 f0 = __half22float2(*(__half2*)&q.x);
        float2 f1 = __half22float2(*(__half2*)&q.y);
        float2 f2 = __half22float2(*(__half2*)&q.z);
        float2 f3 = __half22float2(*(__half2*)&q.w);
        r.a[0] = fmaf(v, f0.x, r.a[0]); r.a[1] = fmaf(v, f0.y, r.a[1]);
        r.a[2] = fmaf(v, f1.x, r.a[2]); r.a[3] = fmaf(v, f1.y, r.a[3]);
        r.a[4] = fmaf(v, f2.x, r.a[4]); r.a[5] = fmaf(v, f2.y, r.a[5]);
        r.a[6] = fmaf(v, f3.x, r.a[6]); r.a[7] = fmaf(v, f3.y, r.a[7]);
    }
#pragma unroll
    for (int k = 0; k < 8; k++) {
        r.a[k] += __shfl_xor_sync(0xffffffff, r.a[k], 8);
        r.a[k] += __shfl_xor_sync(0xffffffff, r.a[k], 16);
    }
    return r;
}

__device__ __forceinline__ uint4 pack_half8(const Acc8& r)
{
    uint4 o;
    *(__half2*)&o.x = __floats2half2_rn(r.a[0], r.a[1]);
    *(__half2*)&o.y = __floats2half2_rn(r.a[2], r.a[3]);
    *(__half2*)&o.z = __floats2half2_rn(r.a[4], r.a[5]);
    *(__half2*)&o.w = __floats2half2_rn(r.a[6], r.a[7]);
    return o;
}

// user side: yh[r] = sum val_j * xh[idx_j]
__global__ void __launch_bounds__(256) spmm_user(
    const __half* __restrict__ xh, __half* __restrict__ yh,
    const int2* __restrict__ ev, const int* __restrict__ ptr)
{
    int r = blockIdx.x * 8 + (threadIdx.x >> 5);
    if (r >= N_USERS) return;
    int lane = threadIdx.x & 31, g = lane >> 3, sl = lane & 7;
    int j0 = __ldg(&ptr[r]), e = __ldg(&ptr[r + 1]);
    Acc8 s = gather_row(xh, ev, j0, e, g, sl);
    if (g == 0)
        ((uint4*)(yh + ((size_t)r << 6)))[sl] = pack_half8(s);
}

// item side, first lap: z = seg_sum(yh); t1 = t0 - 2z; acc = c0*t0 + c1*t1; th = half(t1)
__global__ void __launch_bounds__(256) spmm_item_first(
    const __half* __restrict__ yh, const int2* __restrict__ ev, const int* __restrict__ ptr,
    const float* __restrict__ t0, float* __restrict__ t1, float* __restrict__ acc,
    __half* __restrict__ th, float c0, float c1)
{
    int r = blockIdx.x * 8 + (threadIdx.x >> 5);
    if (r >= N_ITEMS) return;
    int lane = threadIdx.x & 31, g = lane >> 3, sl = lane & 7;
    int j0 = __ldg(&ptr[r]), e = __ldg(&ptr[r + 1]);
    Acc8 z = gather_row(yh, ev, j0, e, g, sl);
    if (g == 0) {
        size_t o = ((size_t)r << 6) + (size_t)sl * 8;
        Acc8 b;
#pragma unroll
        for (int h = 0; h < 2; h++) {
            float4 a = *(const float4*)(t0 + o + h * 4);
            float4 bb, oo;
            bb.x = a.x - 2.f * z.a[h*4+0]; bb.y = a.y - 2.f * z.a[h*4+1];
            bb.z = a.z - 2.f * z.a[h*4+2]; bb.w = a.w - 2.f * z.a[h*4+3];
            *(float4*)(t1 + o + h * 4) = bb;
            oo.x = c0 * a.x + c1 * bb.x; oo.y = c0 * a.y + c1 * bb.y;
            oo.z = c0 * a.z + c1 * bb.z; oo.w = c0 * a.w + c1 * bb.w;
            *(float4*)(acc + o + h * 4) = oo;
            b.a[h*4+0] = bb.x; b.a[h*4+1] = bb.y; b.a[h*4+2] = bb.z; b.a[h*4+3] = bb.w;
        }
        *(uint4*)(th + o) = pack_half8(b);
    }
}

// item side, step: z = seg_sum(yh); t2 = 2*t1 - 4z - t0 (in place over t0);
// acc += ck*t2; th = half(t2)
__global__ void __launch_bounds__(256) spmm_item_step(
    const __half* __restrict__ yh, const int2* __restrict__ ev, const int* __restrict__ ptr,
    float* __restrict__ t0io, const float* __restrict__ t1, float* __restrict__ acc,
    __half* __restrict__ th, float ck)
{
    int r = blockIdx.x * 8 + (threadIdx.x >> 5);
    if (r >= N_ITEMS) return;
    int lane = threadIdx.x & 31, g = lane >> 3, sl = lane & 7;
    int j0 = __ldg(&ptr[r]), e = __ldg(&ptr[r + 1]);
    Acc8 z = gather_row(yh, ev, j0, e, g, sl);
    if (g == 0) {
        size_t o = ((size_t)r << 6) + (size_t)sl * 8;
        Acc8 t2;
#pragma unroll
        for (int h = 0; h < 2; h++) {
            float4 a = *(const float4*)(t0io + o + h * 4);
            float4 b = *(const float4*)(t1 + o + h * 4);
            float4 t;
            t.x = 2.f * b.x - 4.f * z.a[h*4+0] - a.x;
            t.y = 2.f * b.y - 4.f * z.a[h*4+1] - a.y;
            t.z = 2.f * b.z - 4.f * z.a[h*4+2] - a.z;
            t.w = 2.f * b.w - 4.f * z.a[h*4+3] - a.w;
            *(float4*)(t0io + o + h * 4) = t;
            float4 oc = *(const float4*)(acc + o + h * 4);
            oc.x += ck * t.x; oc.y += ck * t.y; oc.z += ck * t.z; oc.w += ck * t.w;
            *(float4*)(acc + o + h * 4) = oc;
            t2.a[h*4+0] = t.x; t2.a[h*4+1] = t.y; t2.a[h*4+2] = t.z; t2.a[h*4+3] = t.w;
        }
        *(uint4*)(th + o) = pack_half8(t2);
    }
}

// ---------------- host: replicate cheby_coeffs in double ----------------------
static void compute_coeffs(float c[ORDER + 1])
{
    const int order = ORDER;
    double tgt[ORDER + 1], nodes[ORDER + 1];
    for (int x = 0; x <= order; x++) {
        double v = cos((double)(order - x) / order * M_PI);
        v = nearbyint(v * 1000.0) / 1000.0;
        double t = (v < 0.0) ? pow(-v, (double)FLATNESS) * 0.5 + 0.5
                             : pow(v, (double)FLATNESS) * (-0.5) + 0.5;
        tgt[x] = nearbyint(t * 1000.0) / 1000.0;
    }
    for (int k = 1; k <= order + 1; k++)
        nodes[k - 1] = cos((order + 1 + 0.5 - k) / (double)(order + 1) * M_PI);

    double P0[ORDER + 1], P1[ORDER + 1], P2[ORDER + 1];
    double s0 = 0.0, s1 = 0.0;
    for (int i = 0; i <= order; i++) {
        P0[i] = tgt[i];
        P1[i] = nodes[i] * tgt[i];
        s0 += P0[i]; s1 += P1[i];
    }
    c[0] = (float)(s0 * (2.0 / (order + 1)) / 2.0);
    c[1] = (float)(s1 * (2.0 / (order + 1)));
    for (int k = 2; k <= order; k++) {
        double s = 0.0;
        for (int i = 0; i <= order; i++) {
            P2[i] = 2.0 * nodes[i] * P1[i] - P0[i];
            s += P2[i];
        }
        c[k] = (float)(s * (2.0 / (order + 1)));
        for (int i = 0; i <= order; i++) { P0[i] = P1[i]; P1[i] = P2[i]; }
    }
}

// ---------------- launch ------------------------------------------------------
extern "C" void kernel_launch(void* const* d_in, const int* in_sizes, int n_in,
                              void* d_out, int out_size)
{
    const float* signal = (const float*)d_in[0];
    const float* vals   = (const float*)d_in[1];
    const int*   row    = (const int*)d_in[2];
    const int*   col    = (const int*)d_in[3];
    const int    nnz    = in_sizes[1];

    float c[ORDER + 1];
    compute_coeffs(c);

    float *ta, *tb, *acc;
    __half *yh, *th;
    int *ptru, *ptri, *curu, *curi, *part;
    int2 *evr, *evc;
    cudaGetSymbolAddress((void**)&ta,   g_ta);
    cudaGetSymbolAddress((void**)&tb,   g_tb);
    cudaGetSymbolAddress((void**)&acc,  g_acc);
    cudaGetSymbolAddress((void**)&yh,   g_yh);
    cudaGetSymbolAddress((void**)&th,   g_th);
    cudaGetSymbolAddress((void**)&ptru, g_ptru);
    cudaGetSymbolAddress((void**)&ptri, g_ptri);
    cudaGetSymbolAddress((void**)&curu, g_curu);
    cudaGetSymbolAddress((void**)&curi, g_curi);
    cudaGetSymbolAddress((void**)&part, g_part);
    cudaGetSymbolAddress((void**)&evr,  g_evr);
    cudaGetSymbolAddress((void**)&evc,  g_evc);

    dim3 tblk(32, 8);
    dim3 tgrd((N_ITEMS + 31) / 32, (BATCH + 31) / 32);

    const int eblk = (nnz + 255) / 256;
    const int nbu  = (N_USERS + SCAN_T * SCAN_E - 1) / (SCAN_T * SCAN_E);
    const int nbi  = (N_ITEMS + SCAN_T * SCAN_E - 1) / (SCAN_T * SCAN_E);
    const int p3u  = (N_USERS + 1023) / 1024;
    const int p3i  = (N_ITEMS + 1023) / 1024;
    const int gu   = (N_USERS + 7) / 8;
    const int gi   = (N_ITEMS + 7) / 8;

    // ---- preprocessing: CSR (by user) + CSC (by item) ----
    cudaMemsetAsync(curu, 0, sizeof(int) * N_USERS);
    cudaMemsetAsync(curi, 0, sizeof(int) * N_ITEMS);
    hist_kernel<<<eblk, 256>>>(row, col, curu, curi, nnz);

    scan_phase1<<<nbu, SCAN_T>>>(curu, ptru, part, N_USERS);
    scan_phase2<<<1, 32>>>(part, nbu);
    scan_phase3<<<p3u, SCAN_T>>>(ptru, curu, part, N_USERS, nnz);

    scan_phase1<<<nbi, SCAN_T>>>(curi, ptri, part, N_ITEMS);
    scan_phase2<<<1, 32>>>(part, nbi);
    scan_phase3<<<p3i, SCAN_T>>>(ptri, curi, part, N_ITEMS, nnz);

    build_lists<<<eblk, 256>>>(row, col, vals, curu, curi, evr, evc, nnz);

    // ---- signal to item-major (fp32 state + half shadow) ----
    transpose_in<<<tgrd, tblk>>>(signal, ta, th);

    // ---- Chebyshev recurrence, 8 laps ----
    spmm_user<<<gu, 256>>>(th, yh, evr, ptru);
    spmm_item_first<<<gi, 256>>>(yh, evc, ptri, ta, tb, acc, th, c[0], c[1]);

    float* p0 = ta;   // t_{k-2}
    float* p1 = tb;   // t_{k-1}
    for (int k = 2; k <= ORDER; k++) {
        spmm_user<<<gu, 256>>>(th, yh, evr, ptru);
        spmm_item_step<<<gi, 256>>>(yh, evc, ptri, p0, p1, acc, th, c[k]);
        float* t = p0; p0 = p1; p1 = t;
    }

    transpose_out<<<tgrd, tblk>>>(acc, (float*)d_out);
}